// round 2
// baseline (speedup 1.0000x reference)
#include <cuda_runtime.h>
#include <math.h>
#include <stdint.h>

#define Bz 32
#define Tz 512
#define Dz 768
#define Hz 256
#define Gz 1024   // 4*Hz
#define Kz 32

// ---------------- scratch (device globals; no allocation allowed) ----------------
__device__ float  g_pre[2][Tz][Bz][Gz];     // pre-activations, both dirs (134 MB)
__device__ float  g_h[2][Bz][Tz][Hz];       // hidden states at OUTPUT positions (33 MB)
__device__ float  g_em[Bz][Tz][Kz];         // emissions (2 MB)
__device__ float4 g_Wt4[2][Hz][Hz];         // W_hh^T: [dir][k][j] = (row j, H+j, 2H+j, 3H+j) col k
__device__ float  g_WclfT[2 * Hz][Kz];      // W_clf transposed
__device__ float  g_partial[Bz];            // per-batch (num - logZ)

__device__ __forceinline__ float sigm(float x) { return 1.0f / (1.0f + expf(-x)); }

// ---------------- prep: weight transposes ----------------
__global__ void prep_kernel(const float* __restrict__ Whf, const float* __restrict__ Whb,
                            const float* __restrict__ Wclf) {
    int idx = blockIdx.x * blockDim.x + threadIdx.x;
    if (idx < 2 * Hz * Hz) {
        int dir = idx / (Hz * Hz);
        int rem = idx % (Hz * Hz);
        int k = rem / Hz, j = rem % Hz;
        const float* W = dir ? Whb : Whf;
        g_Wt4[dir][k][j] = make_float4(W[(size_t)j * Hz + k],
                                       W[(size_t)(Hz + j) * Hz + k],
                                       W[(size_t)(2 * Hz + j) * Hz + k],
                                       W[(size_t)(3 * Hz + j) * Hz + k]);
    } else {
        int r = idx - 2 * Hz * Hz;
        if (r < 2 * Hz * Kz) {
            int j = r / Kz, k = r % Kz;
            g_WclfT[j][k] = Wclf[(size_t)k * (2 * Hz) + j];
        }
    }
}

// ---------------- input GEMM: g_pre[dir][t][b][g] = x[b][t,:] . W_ih[dir][g,:] + bias[g] ----
// Rows r = t*32+b (M=16384), cols g (N=1024), K=768. 128x128x16 tiles, 8x8 microtile.
__global__ __launch_bounds__(256) void gemm_pre_kernel(
    const float* __restrict__ x,
    const float* __restrict__ Wf, const float* __restrict__ Wb,
    const float* __restrict__ bf, const float* __restrict__ bb)
{
    const int dir = blockIdx.z;
    const float* __restrict__ W    = dir ? Wb : Wf;
    const float* __restrict__ bias = dir ? bb : bf;

    __shared__ float As[16][132];
    __shared__ float Bs[16][132];

    const int tid = threadIdx.x;
    const int tx = tid & 15, ty = tid >> 4;
    const int row0 = blockIdx.y * 128;
    const int col0 = blockIdx.x * 128;

    float acc[8][8];
#pragma unroll
    for (int i = 0; i < 8; i++)
#pragma unroll
        for (int j = 0; j < 8; j++) acc[i][j] = 0.f;

    for (int k0 = 0; k0 < Dz; k0 += 16) {
#pragma unroll
        for (int l = 0; l < 2; l++) {
            int f4 = tid + (l << 8);          // 0..511
            int m  = f4 >> 2;                 // tile row 0..127
            int kc = (f4 & 3) << 2;           // k offset 0,4,8,12
            int r = row0 + m;
            const float4 av = *(const float4*)(x + ((size_t)(r & 31) * Tz + (size_t)(r >> 5)) * Dz + k0 + kc);
            As[kc + 0][m] = av.x; As[kc + 1][m] = av.y; As[kc + 2][m] = av.z; As[kc + 3][m] = av.w;
            const float4 bv = *(const float4*)(W + (size_t)(col0 + m) * Dz + k0 + kc);
            Bs[kc + 0][m] = bv.x; Bs[kc + 1][m] = bv.y; Bs[kc + 2][m] = bv.z; Bs[kc + 3][m] = bv.w;
        }
        __syncthreads();
#pragma unroll
        for (int kk = 0; kk < 16; kk++) {
            float a[8], w[8];
            *(float4*)(a)     = *(const float4*)&As[kk][ty * 8];
            *(float4*)(a + 4) = *(const float4*)&As[kk][ty * 8 + 4];
            *(float4*)(w)     = *(const float4*)&Bs[kk][tx * 8];
            *(float4*)(w + 4) = *(const float4*)&Bs[kk][tx * 8 + 4];
#pragma unroll
            for (int i = 0; i < 8; i++)
#pragma unroll
                for (int j = 0; j < 8; j++) acc[i][j] += a[i] * w[j];
        }
        __syncthreads();
    }

    float4 bia = *(const float4*)(bias + col0 + tx * 8);
    float4 bib = *(const float4*)(bias + col0 + tx * 8 + 4);
    float* outp = &g_pre[0][0][0][0] + (size_t)dir * Tz * Bz * Gz;
#pragma unroll
    for (int i = 0; i < 8; i++) {
        int r = row0 + ty * 8 + i;
        float* op = outp + (size_t)r * Gz + col0 + tx * 8;
        float4 v0 = make_float4(acc[i][0] + bia.x, acc[i][1] + bia.y, acc[i][2] + bia.z, acc[i][3] + bia.w);
        float4 v1 = make_float4(acc[i][4] + bib.x, acc[i][5] + bib.y, acc[i][6] + bib.z, acc[i][7] + bib.w);
        *(float4*)(op)     = v0;
        *(float4*)(op + 4) = v1;
    }
}

// ---------------- LSTM recurrence: one CTA per (batch-pair, dir), 256 threads ----------------
__global__ __launch_bounds__(256) void lstm_kernel(const int* __restrict__ lengths)
{
    const int bpair = blockIdx.x;            // 0..15
    const int dir   = blockIdx.y;            // 0..1
    const int b0 = bpair * 2, b1 = b0 + 1;
    const int j = threadIdx.x;

    __shared__ float h0s[2][Hz];
    __shared__ float h1s[2][Hz];

    h0s[0][j] = 0.f; h1s[0][j] = 0.f;
    float c0 = 0.f, c1 = 0.f;
    __syncthreads();

    const int len0 = lengths[b0];
    const int len1 = lengths[b1];
    const float4* __restrict__ Wp = &g_Wt4[dir][0][j];
    const float* __restrict__ preb = &g_pre[0][0][0][0] + (size_t)dir * Tz * Bz * Gz;
    float* __restrict__ hout = &g_h[0][0][0][0] + (size_t)dir * Bz * Tz * Hz;

    int pbuf = 0;
    for (int t = 0; t < Tz; t++) {
        int ti0 = (dir == 0) ? t : ((t < len0) ? (len0 - 1 - t) : t);
        int ti1 = (dir == 0) ? t : ((t < len1) ? (len1 - 1 - t) : t);

        const float* p0 = preb + ((size_t)ti0 * Bz + b0) * Gz;
        const float* p1 = preb + ((size_t)ti1 * Bz + b1) * Gz;
        float4 a0 = make_float4(p0[j], p0[Hz + j], p0[2 * Hz + j], p0[3 * Hz + j]);
        float4 a1 = make_float4(p1[j], p1[Hz + j], p1[2 * Hz + j], p1[3 * Hz + j]);

        const float* hc0 = h0s[pbuf];
        const float* hc1 = h1s[pbuf];
#pragma unroll 8
        for (int k = 0; k < Hz; k++) {
            float4 w = Wp[(size_t)k * Hz];
            float ha = hc0[k];
            float hb = hc1[k];
            a0.x += ha * w.x; a0.y += ha * w.y; a0.z += ha * w.z; a0.w += ha * w.w;
            a1.x += hb * w.x; a1.y += hb * w.y; a1.z += hb * w.z; a1.w += hb * w.w;
        }

        float i0 = sigm(a0.x), f0 = sigm(a0.y), g0 = tanhf(a0.z), o0 = sigm(a0.w);
        c0 = f0 * c0 + i0 * g0;
        float hv0 = o0 * tanhf(c0);
        float i1 = sigm(a1.x), f1 = sigm(a1.y), g1 = tanhf(a1.z), o1 = sigm(a1.w);
        c1 = f1 * c1 + i1 * g1;
        float hv1 = o1 * tanhf(c1);

        h0s[pbuf ^ 1][j] = hv0;
        h1s[pbuf ^ 1][j] = hv1;
        hout[((size_t)b0 * Tz + ti0) * Hz + j] = hv0;   // rev_idx is an involution
        hout[((size_t)b1 * Tz + ti1) * Hz + j] = hv1;
        pbuf ^= 1;
        __syncthreads();
    }
}

// ---------------- emissions: em[b][t][k] = hcat . WclfT[:,k] + b_clf[k] ----------------
__global__ __launch_bounds__(256) void emis_kernel(const float* __restrict__ b_clf)
{
    int gw = (blockIdx.x * blockDim.x + threadIdx.x) >> 5;   // 0..16383  (b*512+t)
    int lane = threadIdx.x & 31;
    int b = gw >> 9, t = gw & 511;

    float acc = b_clf[lane];
#pragma unroll
    for (int half = 0; half < 2; half++) {
        const float* hb = &g_h[half][b][t][0];
        for (int j0 = 0; j0 < Hz; j0 += 32) {
            float hv = hb[j0 + lane];
#pragma unroll
            for (int jj = 0; jj < 32; jj++) {
                float hj = __shfl_sync(0xffffffffu, hv, jj);
                acc += hj * g_WclfT[half * Hz + j0 + jj][lane];
            }
        }
    }
    g_em[b][t][lane] = acc;
}

// ---------------- CRF NLL: one warp per batch ----------------
__global__ __launch_bounds__(32) void crf_nll_kernel(
    const int* __restrict__ lengths, const int* __restrict__ targets,
    const float* __restrict__ start_t, const float* __restrict__ end_t,
    const float* __restrict__ trans)
{
    const int b = blockIdx.x;
    const int lane = threadIdx.x;
    __shared__ float alpha_s[32];

    float tc[32];                 // trans[k][lane], k = 0..31
#pragma unroll
    for (int k = 0; k < 32; k++) tc[k] = trans[k * Kz + lane];

    const int len = lengths[b];
    const int* tgt = targets + (size_t)b * Tz;
    const float* em = &g_em[b][0][0];

    // numerator
    float part = 0.f;
    for (int t = lane; t < Tz; t += 32) {
        int tg = tgt[t];
        if (t == 0) {
            part += start_t[tg] + em[tg];
        } else if (t < len) {
            int tp = tgt[t - 1];
            part += trans[tp * Kz + tg] + em[t * Kz + tg];
        }
    }
#pragma unroll
    for (int off = 16; off >= 1; off >>= 1)
        part += __shfl_xor_sync(0xffffffffu, part, off);
    part += end_t[tgt[len - 1]];   // same on all lanes

    // forward logsumexp scan
    float alpha = start_t[lane] + em[lane];
    for (int t = 1; t < len; t++) {
        alpha_s[lane] = alpha;
        __syncwarp();
        float m = -3.0e38f;
#pragma unroll
        for (int k = 0; k < 32; k++) m = fmaxf(m, alpha_s[k] + tc[k]);
        float s = 0.f;
#pragma unroll
        for (int k = 0; k < 32; k++) s += __expf(alpha_s[k] + tc[k] - m);
        alpha = m + __logf(s) + em[t * Kz + lane];
        __syncwarp();
    }
    float v = alpha + end_t[lane];
    float M = v;
#pragma unroll
    for (int off = 16; off >= 1; off >>= 1)
        M = fmaxf(M, __shfl_xor_sync(0xffffffffu, M, off));
    float S = __expf(v - M);
#pragma unroll
    for (int off = 16; off >= 1; off >>= 1)
        S += __shfl_xor_sync(0xffffffffu, S, off);
    float logZ = M + __logf(S);

    if (lane == 0) g_partial[b] = part - logZ;
}

__global__ __launch_bounds__(32) void finalize_kernel(float* __restrict__ out)
{
    int lane = threadIdx.x;
    float p = g_partial[lane];
#pragma unroll
    for (int off = 16; off >= 1; off >>= 1)
        p += __shfl_xor_sync(0xffffffffu, p, off);
    if (lane == 0) out[0] = -p / (float)Bz;
}

// ---------------- Viterbi: one warp per batch ----------------
__global__ __launch_bounds__(32) void viterbi_kernel(
    const int* __restrict__ lengths,
    const float* __restrict__ start_t, const float* __restrict__ end_t,
    const float* __restrict__ trans, float* __restrict__ out)
{
    const int b = blockIdx.x;
    const int lane = threadIdx.x;
    __shared__ float score_s[32];
    __shared__ uint8_t hist[Tz - 1][32];
    __shared__ int last_sh;

    float tc[32];
#pragma unroll
    for (int k = 0; k < 32; k++) tc[k] = trans[k * Kz + lane];

    const int len = lengths[b];
    const float* em = &g_em[b][0][0];

    float score = start_t[lane] + em[lane];
    for (int t = 1; t < len; t++) {
        score_s[lane] = score;
        __syncwarp();
        float best = -3.0e38f;
        int bi = 0;
#pragma unroll
        for (int k = 0; k < 32; k++) {
            float v = score_s[k] + tc[k];
            if (v > best) { best = v; bi = k; }   // strict > : first-index tiebreak
        }
        score = best + em[t * Kz + lane];
        hist[t - 1][lane] = (uint8_t)bi;
        __syncwarp();
    }

    score_s[lane] = score + end_t[lane];
    __syncwarp();
    if (lane == 0) {
        float best = -3.0e38f;
        int bi = 0;
#pragma unroll
        for (int k = 0; k < 32; k++) {
            if (score_s[k] > best) { best = score_s[k]; bi = k; }
        }
        last_sh = bi;
    }
    __syncwarp();

    if (lane == 0) {
        float* op = out + 1 + (size_t)b * Tz;
        int cur = last_sh;
        for (int t = Tz - 1; t >= 1; t--) {
            op[t] = (t < len) ? (float)cur : 0.0f;
            if (t < len) cur = (int)hist[t - 1][cur];   // identity backpointers past len
        }
        op[0] = (float)cur;
    }
}

// ---------------- launch ----------------
extern "C" void kernel_launch(void* const* d_in, const int* in_sizes, int n_in,
                              void* d_out, int out_size)
{
    const float* x       = (const float*)d_in[0];
    const int*   lengths = (const int*)  d_in[1];
    // d_in[2] = mask (recomputed from lengths)
    const int*   targets = (const int*)  d_in[3];
    const float* W_ih_f  = (const float*)d_in[4];
    const float* W_hh_f  = (const float*)d_in[5];
    const float* b_f     = (const float*)d_in[6];
    const float* W_ih_b  = (const float*)d_in[7];
    const float* W_hh_b  = (const float*)d_in[8];
    const float* b_b     = (const float*)d_in[9];
    const float* W_clf   = (const float*)d_in[10];
    const float* b_clf   = (const float*)d_in[11];
    const float* start_t = (const float*)d_in[12];
    const float* end_t   = (const float*)d_in[13];
    const float* trans   = (const float*)d_in[14];
    float* out = (float*)d_out;

    prep_kernel<<<576, 256>>>(W_hh_f, W_hh_b, W_clf);

    dim3 ggrid(Gz / 128, (Tz * Bz) / 128, 2);
    gemm_pre_kernel<<<ggrid, 256>>>(x, W_ih_f, W_ih_b, b_f, b_b);

    dim3 lgrid(Bz / 2, 2);
    lstm_kernel<<<lgrid, 256>>>(lengths);

    emis_kernel<<<(Bz * Tz) / 8, 256>>>(b_clf);

    crf_nll_kernel<<<Bz, 32>>>(lengths, targets, start_t, end_t, trans);
    finalize_kernel<<<1, 32>>>(out);
    viterbi_kernel<<<Bz, 32>>>(lengths, start_t, end_t, trans, out);
}

// round 3
// speedup vs baseline: 3.8726x; 3.8726x over previous
#include <cuda_runtime.h>
#include <math.h>
#include <stdint.h>

#define Bz 32
#define Tz 512
#define Dz 768
#define Hz 256
#define Gz 1024   // 4*Hz
#define Kz 32
#define NCTA 128  // persistent LSTM CTAs (2 dirs x 64 j-slices)
#define JP 4      // hidden units per CTA

// ---------------- scratch (device globals; no allocation allowed) ----------------
__device__ float  g_pre[2][Tz][Bz][Gz];     // pre-activations (134 MB)
__device__ float  g_h[2][Bz][Tz][Hz];       // hidden states at OUTPUT positions (33 MB)
__device__ float  g_em[Bz][Tz][Kz];         // emissions (2 MB)
__device__ float  g_WclfT[2 * Hz][Kz];      // W_clf transposed
__device__ float  g_partial[Bz];            // per-batch (num - logZ)
__device__ float  g_xr[Tz * Bz][Dz];        // x re-laid-out: row r = t*32+b (50 MB)
__device__ float  g_hT[2][2][Hz][Bz];       // h broadcast ping-pong: [parity][dir][k][b]
__device__ unsigned g_sync[Tz];             // per-step arrival counters (memset each launch)

__device__ __forceinline__ float sigm(float x) { return 1.0f / (1.0f + expf(-x)); }

// ---------------- prep: W_clf transpose ----------------
__global__ void prep_kernel(const float* __restrict__ Wclf) {
    int r = blockIdx.x * blockDim.x + threadIdx.x;
    if (r < 2 * Hz * Kz) {
        int j = r / Kz, k = r % Kz;
        g_WclfT[j][k] = Wclf[(size_t)k * (2 * Hz) + j];
    }
}

// ---------------- x relayout: xr[t*32+b][d] = x[b][t][d] ----------------
__global__ __launch_bounds__(192) void xr_kernel(const float* __restrict__ x) {
    int r = blockIdx.x;                 // 0..16383
    int b = r & 31, t = r >> 5;
    const float4* src = (const float4*)(x + ((size_t)b * Tz + t) * Dz);
    float4* dst = (float4*)(&g_xr[r][0]);
    dst[threadIdx.x] = src[threadIdx.x];
}

// ---------------- input GEMM: g_pre[dir][t][b][g] = xr[r,:] . W_ih[dir][g,:] + bias ----
__global__ __launch_bounds__(256) void gemm_pre_kernel(
    const float* __restrict__ Wf, const float* __restrict__ Wb,
    const float* __restrict__ bf, const float* __restrict__ bb)
{
    const int dir = blockIdx.z;
    const float* __restrict__ W    = dir ? Wb : Wf;
    const float* __restrict__ bias = dir ? bb : bf;

    __shared__ float As[16][132];
    __shared__ float Bs[16][132];

    const int tid = threadIdx.x;
    const int tx = tid & 15, ty = tid >> 4;
    const int row0 = blockIdx.y * 128;
    const int col0 = blockIdx.x * 128;

    float acc[8][8];
#pragma unroll
    for (int i = 0; i < 8; i++)
#pragma unroll
        for (int j = 0; j < 8; j++) acc[i][j] = 0.f;

    for (int k0 = 0; k0 < Dz; k0 += 16) {
#pragma unroll
        for (int l = 0; l < 2; l++) {
            int f4 = tid + (l << 8);          // 0..511
            int m  = f4 >> 2;                 // tile row 0..127
            int kc = (f4 & 3) << 2;           // k offset 0,4,8,12
            const float4 av = *(const float4*)(&g_xr[row0 + m][k0 + kc]);
            As[kc + 0][m] = av.x; As[kc + 1][m] = av.y; As[kc + 2][m] = av.z; As[kc + 3][m] = av.w;
            const float4 bv = *(const float4*)(W + (size_t)(col0 + m) * Dz + k0 + kc);
            Bs[kc + 0][m] = bv.x; Bs[kc + 1][m] = bv.y; Bs[kc + 2][m] = bv.z; Bs[kc + 3][m] = bv.w;
        }
        __syncthreads();
#pragma unroll
        for (int kk = 0; kk < 16; kk++) {
            float a[8], w[8];
            *(float4*)(a)     = *(const float4*)&As[kk][ty * 8];
            *(float4*)(a + 4) = *(const float4*)&As[kk][ty * 8 + 4];
            *(float4*)(w)     = *(const float4*)&Bs[kk][tx * 8];
            *(float4*)(w + 4) = *(const float4*)&Bs[kk][tx * 8 + 4];
#pragma unroll
            for (int i = 0; i < 8; i++)
#pragma unroll
                for (int j = 0; j < 8; j++) acc[i][j] += a[i] * w[j];
        }
        __syncthreads();
    }

    float4 bia = *(const float4*)(bias + col0 + tx * 8);
    float4 bib = *(const float4*)(bias + col0 + tx * 8 + 4);
    float* outp = &g_pre[0][0][0][0] + (size_t)dir * Tz * Bz * Gz;
#pragma unroll
    for (int i = 0; i < 8; i++) {
        int r = row0 + ty * 8 + i;
        float* op = outp + (size_t)r * Gz + col0 + tx * 8;
        *(float4*)(op)     = make_float4(acc[i][0] + bia.x, acc[i][1] + bia.y, acc[i][2] + bia.z, acc[i][3] + bia.w);
        *(float4*)(op + 4) = make_float4(acc[i][4] + bib.x, acc[i][5] + bib.y, acc[i][6] + bib.z, acc[i][7] + bib.w);
    }
}

// ---------------- persistent LSTM: full-chip, grid-synced per step ----------------
// CTA = (dir, j-slice of 4 hidden units). Weights (16 rows x 256) live in smem.
// Each step: stage h (all K=256, all B=32) from global ping-pong buffer, GEMV,
// activations on threads 0..127, publish h, spin-barrier on g_sync[t].
#define WS_STRIDE 260
#define SMEM_FLOATS (16*WS_STRIDE + 256*32 + 16*32 + 16*32 + 32)

__global__ __launch_bounds__(256) void lstm_persist(
    const float* __restrict__ Whf, const float* __restrict__ Whb,
    const int* __restrict__ lengths)
{
    extern __shared__ float smem[];
    float* ws  = smem;                    // [16][260]
    float* hs  = ws + 16 * WS_STRIDE;     // [256][32]
    float* red = hs + 256 * 32;           // [16][32]
    float* act = red + 16 * 32;           // [16][32]
    int*   ls  = (int*)(act + 16 * 32);   // [32]

    const int cta = blockIdx.x;
    const int dir = cta >> 6;
    const int jc  = cta & 63;
    const int j0  = jc * JP;
    const int tid = threadIdx.x;

    const float* __restrict__ W = dir ? Whb : Whf;
    // fill weight slice: ws[gr][k] = W_hh[gate*256 + j0 + jj][k], gr = gate*4+jj
    for (int i = tid; i < 16 * Hz; i += 256) {
        int gr = i >> 8;
        int k  = i & 255;
        int grow = (gr >> 2) * Hz + j0 + (gr & 3);
        ws[gr * WS_STRIDE + k] = W[(size_t)grow * Hz + k];
    }
    if (tid < 32) ls[tid] = lengths[tid];
    __syncthreads();

    // FMA-role indices
    const int kh = tid >> 7;          // k-half 0/1
    const int gr = (tid >> 3) & 15;   // gate-row 0..15
    const int bq = tid & 7;           // batch-quad 0..7
    const float* wrow = ws + gr * WS_STRIDE + kh * 128;
    const float* hrow = hs + kh * 128 * 32 + bq * 4;
    const float* __restrict__ preb = &g_pre[0][0][0][0] + (size_t)dir * Tz * Bz * Gz;

    // cell state for activation threads (tid < 128): jj = tid>>5, b = tid&31
    float c = 0.f;
    const int a_jj = tid >> 5;
    const int a_b  = tid & 31;
    const int a_len = (tid < 128) ? ls[a_b] : 0;

    int par = 0;
    for (int t = 0; t < Tz; t++) {
        // stage h broadcast buffer (32 KB) into smem
        {
            const float4* hsrc = (const float4*)(&g_hT[par][dir][0][0]);
            float4* hdst = (float4*)hs;
#pragma unroll
            for (int i = 0; i < 8; i++)
                hdst[tid + i * 256] = hsrc[tid + i * 256];
        }
        // preload pre-activations for the kh==0 accumulator threads
        float p0 = 0.f, p1 = 0.f, p2 = 0.f, p3 = 0.f;
        if (kh == 0) {
            int grow = (gr >> 2) * Hz + j0 + (gr & 3);
            int b0 = bq * 4;
            int l0 = ls[b0], l1 = ls[b0+1], l2 = ls[b0+2], l3 = ls[b0+3];
            int ti0 = (dir && t < l0) ? (l0 - 1 - t) : t;
            int ti1 = (dir && t < l1) ? (l1 - 1 - t) : t;
            int ti2 = (dir && t < l2) ? (l2 - 1 - t) : t;
            int ti3 = (dir && t < l3) ? (l3 - 1 - t) : t;
            p0 = preb[((size_t)ti0 * Bz + b0 + 0) * Gz + grow];
            p1 = preb[((size_t)ti1 * Bz + b0 + 1) * Gz + grow];
            p2 = preb[((size_t)ti2 * Bz + b0 + 2) * Gz + grow];
            p3 = preb[((size_t)ti3 * Bz + b0 + 3) * Gz + grow];
        }
        __syncthreads();

        // GEMV: 4 batch-accumulators over 128 k
        float a0 = 0.f, a1 = 0.f, a2 = 0.f, a3 = 0.f;
#pragma unroll 4
        for (int k = 0; k < 128; k++) {
            float w = wrow[k];
            float4 h4 = *(const float4*)(hrow + k * 32);
            a0 += w * h4.x; a1 += w * h4.y; a2 += w * h4.z; a3 += w * h4.w;
        }
        if (kh == 1)
            *(float4*)&red[gr * 32 + bq * 4] = make_float4(a0, a1, a2, a3);
        __syncthreads();
        if (kh == 0) {
            float4 r4 = *(const float4*)&red[gr * 32 + bq * 4];
            act[gr * 32 + bq * 4 + 0] = a0 + r4.x + p0;
            act[gr * 32 + bq * 4 + 1] = a1 + r4.y + p1;
            act[gr * 32 + bq * 4 + 2] = a2 + r4.z + p2;
            act[gr * 32 + bq * 4 + 3] = a3 + r4.w + p3;
        }
        __syncthreads();

        // activations + state update + publish (threads 0..127)
        if (tid < 128) {
            float gi = act[(0  + a_jj) * 32 + a_b];
            float gf = act[(4  + a_jj) * 32 + a_b];
            float gg = act[(8  + a_jj) * 32 + a_b];
            float go = act[(12 + a_jj) * 32 + a_b];
            c = sigm(gf) * c + sigm(gi) * tanhf(gg);
            float hv = sigm(go) * tanhf(c);
            g_hT[par ^ 1][dir][j0 + a_jj][a_b] = hv;
            int ti = (dir && t < a_len) ? (a_len - 1 - t) : t;
            g_h[dir][a_b][ti][j0 + a_jj] = hv;
        }
        __threadfence();
        __syncthreads();
        if (tid == 0) {
            atomicAdd(&g_sync[t], 1u);
            while (*(volatile unsigned*)&g_sync[t] < NCTA) __nanosleep(64);
        }
        __syncthreads();
        par ^= 1;
    }
}

// ---------------- emissions: em[b][t][k] = hcat . WclfT[:,k] + b_clf[k] ----------------
__global__ __launch_bounds__(256) void emis_kernel(const float* __restrict__ b_clf)
{
    int gw = (blockIdx.x * blockDim.x + threadIdx.x) >> 5;   // b*512+t
    int lane = threadIdx.x & 31;
    int b = gw >> 9, t = gw & 511;

    float acc = b_clf[lane];
#pragma unroll
    for (int half = 0; half < 2; half++) {
        const float* hb = &g_h[half][b][t][0];
        for (int j0 = 0; j0 < Hz; j0 += 32) {
            float hv = hb[j0 + lane];
#pragma unroll
            for (int jj = 0; jj < 32; jj++) {
                float hj = __shfl_sync(0xffffffffu, hv, jj);
                acc += hj * g_WclfT[half * Hz + j0 + jj][lane];
            }
        }
    }
    g_em[b][t][lane] = acc;
}

// ---------------- CRF NLL: one warp per batch ----------------
__global__ __launch_bounds__(32) void crf_nll_kernel(
    const int* __restrict__ lengths, const int* __restrict__ targets,
    const float* __restrict__ start_t, const float* __restrict__ end_t,
    const float* __restrict__ trans)
{
    const int b = blockIdx.x;
    const int lane = threadIdx.x;
    __shared__ float alpha_s[32];

    float tc[32];
#pragma unroll
    for (int k = 0; k < 32; k++) tc[k] = trans[k * Kz + lane];

    const int len = lengths[b];
    const int* tgt = targets + (size_t)b * Tz;
    const float* em = &g_em[b][0][0];

    float part = 0.f;
    for (int t = lane; t < Tz; t += 32) {
        int tg = tgt[t];
        if (t == 0) {
            part += start_t[tg] + em[tg];
        } else if (t < len) {
            int tp = tgt[t - 1];
            part += trans[tp * Kz + tg] + em[t * Kz + tg];
        }
    }
#pragma unroll
    for (int off = 16; off >= 1; off >>= 1)
        part += __shfl_xor_sync(0xffffffffu, part, off);
    part += end_t[tgt[len - 1]];

    float alpha = start_t[lane] + em[lane];
    for (int t = 1; t < len; t++) {
        alpha_s[lane] = alpha;
        __syncwarp();
        float m = -3.0e38f;
#pragma unroll
        for (int k = 0; k < 32; k++) m = fmaxf(m, alpha_s[k] + tc[k]);
        float s = 0.f;
#pragma unroll
        for (int k = 0; k < 32; k++) s += __expf(alpha_s[k] + tc[k] - m);
        alpha = m + __logf(s) + em[t * Kz + lane];
        __syncwarp();
    }
    float v = alpha + end_t[lane];
    float M = v;
#pragma unroll
    for (int off = 16; off >= 1; off >>= 1)
        M = fmaxf(M, __shfl_xor_sync(0xffffffffu, M, off));
    float S = __expf(v - M);
#pragma unroll
    for (int off = 16; off >= 1; off >>= 1)
        S += __shfl_xor_sync(0xffffffffu, S, off);
    float logZ = M + __logf(S);

    if (lane == 0) g_partial[b] = part - logZ;
}

__global__ __launch_bounds__(32) void finalize_kernel(float* __restrict__ out)
{
    int lane = threadIdx.x;
    float p = g_partial[lane];
#pragma unroll
    for (int off = 16; off >= 1; off >>= 1)
        p += __shfl_xor_sync(0xffffffffu, p, off);
    if (lane == 0) out[0] = -p / (float)Bz;
}

// ---------------- Viterbi: one warp per batch ----------------
__global__ __launch_bounds__(32) void viterbi_kernel(
    const int* __restrict__ lengths,
    const float* __restrict__ start_t, const float* __restrict__ end_t,
    const float* __restrict__ trans, float* __restrict__ out)
{
    const int b = blockIdx.x;
    const int lane = threadIdx.x;
    __shared__ float score_s[32];
    __shared__ uint8_t hist[Tz - 1][32];
    __shared__ int last_sh;

    float tc[32];
#pragma unroll
    for (int k = 0; k < 32; k++) tc[k] = trans[k * Kz + lane];

    const int len = lengths[b];
    const float* em = &g_em[b][0][0];

    float score = start_t[lane] + em[lane];
    for (int t = 1; t < len; t++) {
        score_s[lane] = score;
        __syncwarp();
        float best = -3.0e38f;
        int bi = 0;
#pragma unroll
        for (int k = 0; k < 32; k++) {
            float v = score_s[k] + tc[k];
            if (v > best) { best = v; bi = k; }   // strict >: first-index tiebreak
        }
        score = best + em[t * Kz + lane];
        hist[t - 1][lane] = (uint8_t)bi;
        __syncwarp();
    }

    score_s[lane] = score + end_t[lane];
    __syncwarp();
    if (lane == 0) {
        float best = -3.0e38f;
        int bi = 0;
#pragma unroll
        for (int k = 0; k < 32; k++) {
            if (score_s[k] > best) { best = score_s[k]; bi = k; }
        }
        last_sh = bi;
    }
    __syncwarp();

    if (lane == 0) {
        float* op = out + 1 + (size_t)b * Tz;
        int cur = last_sh;
        for (int t = Tz - 1; t >= 1; t--) {
            op[t] = (t < len) ? (float)cur : 0.0f;
            if (t < len) cur = (int)hist[t - 1][cur];
        }
        op[0] = (float)cur;
    }
}

// ---------------- launch ----------------
extern "C" void kernel_launch(void* const* d_in, const int* in_sizes, int n_in,
                              void* d_out, int out_size)
{
    const float* x       = (const float*)d_in[0];
    const int*   lengths = (const int*)  d_in[1];
    const int*   targets = (const int*)  d_in[3];
    const float* W_ih_f  = (const float*)d_in[4];
    const float* W_hh_f  = (const float*)d_in[5];
    const float* b_f     = (const float*)d_in[6];
    const float* W_ih_b  = (const float*)d_in[7];
    const float* W_hh_b  = (const float*)d_in[8];
    const float* b_b     = (const float*)d_in[9];
    const float* W_clf   = (const float*)d_in[10];
    const float* b_clf   = (const float*)d_in[11];
    const float* start_t = (const float*)d_in[12];
    const float* end_t   = (const float*)d_in[13];
    const float* trans   = (const float*)d_in[14];
    float* out = (float*)d_out;

    // reset per-launch state (graph-replay safe)
    void* psync = nullptr; void* phT = nullptr;
    cudaGetSymbolAddress(&psync, g_sync);
    cudaGetSymbolAddress(&phT, g_hT);
    cudaMemsetAsync(psync, 0, sizeof(unsigned) * Tz);
    cudaMemsetAsync(phT, 0, sizeof(float) * 2 * 2 * Hz * Bz);

    prep_kernel<<<64, 256>>>(W_clf);
    xr_kernel<<<Tz * Bz, 192>>>(x);

    dim3 ggrid(Gz / 128, (Tz * Bz) / 128, 2);
    gemm_pre_kernel<<<ggrid, 256>>>(W_ih_f, W_ih_b, b_f, b_b);

    static int smem_set = 0;
    if (!smem_set) {
        cudaFuncSetAttribute(lstm_persist, cudaFuncAttributeMaxDynamicSharedMemorySize,
                             SMEM_FLOATS * (int)sizeof(float));
        smem_set = 1;
    }
    lstm_persist<<<NCTA, 256, SMEM_FLOATS * sizeof(float)>>>(W_hh_f, W_hh_b, lengths);

    emis_kernel<<<(Bz * Tz) / 8, 256>>>(b_clf);

    crf_nll_kernel<<<Bz, 32>>>(lengths, targets, start_t, end_t, trans);
    finalize_kernel<<<1, 32>>>(out);
    viterbi_kernel<<<Bz, 32>>>(lengths, start_t, end_t, trans, out);
}

// round 7
// speedup vs baseline: 4.6626x; 1.2040x over previous
#include <cuda_runtime.h>
#include <math.h>
#include <stdint.h>

#define Bz 32
#define Tz 512
#define Dz 768
#define Hz 256
#define Gz 1024   // 4*Hz
#define Kz 32
#define NCTA 128  // persistent LSTM CTAs (2 dirs x 64 j-slices)
#define JP 4      // hidden units per CTA

// ---------------- scratch (device globals; no allocation allowed) ----------------
__device__ float  g_pre[2][Tz][Bz][Gz];     // pre-activations (134 MB)
__device__ float  g_h[2][Bz][Tz][Hz];       // hidden states at OUTPUT positions (33 MB)
__device__ float  g_em[Bz][Tz][Kz];         // emissions (2 MB)
__device__ float  g_WclfT[2 * Hz][Kz];      // W_clf transposed
__device__ float  g_partial[Bz];            // per-batch (num - logZ)
__device__ float  g_xr[Tz * Bz][Dz];        // x re-laid-out: row r = t*32+b (50 MB)
__device__ float  g_hT[2][2][Hz][Bz];       // h broadcast ping-pong: [parity][dir][k][b]
__device__ unsigned g_sync[2][Tz];          // per-dir per-step arrival counters

__device__ __forceinline__ float sigm(float x) { return 1.0f / (1.0f + expf(-x)); }

// ---------------- prep: W_clf transpose ----------------
__global__ void prep_kernel(const float* __restrict__ Wclf) {
    int r = blockIdx.x * blockDim.x + threadIdx.x;
    if (r < 2 * Hz * Kz) {
        int j = r / Kz, k = r % Kz;
        g_WclfT[j][k] = Wclf[(size_t)k * (2 * Hz) + j];
    }
}

// ---------------- x relayout: xr[t*32+b][d] = x[b][t][d] ----------------
__global__ __launch_bounds__(192) void xr_kernel(const float* __restrict__ x) {
    int r = blockIdx.x;                 // 0..16383
    int b = r & 31, t = r >> 5;
    const float4* src = (const float4*)(x + ((size_t)b * Tz + t) * Dz);
    float4* dst = (float4*)(&g_xr[r][0]);
    dst[threadIdx.x] = src[threadIdx.x];
}

// ---------------- input GEMM (software-pipelined): pre = xr . W_ih^T + bias ----
__global__ __launch_bounds__(256) void gemm_pre_kernel(
    const float* __restrict__ Wf, const float* __restrict__ Wb,
    const float* __restrict__ bf, const float* __restrict__ bb)
{
    const int dir = blockIdx.z;
    const float* __restrict__ W    = dir ? Wb : Wf;
    const float* __restrict__ bias = dir ? bb : bf;

    __shared__ float As[16][132];
    __shared__ float Bs[16][132];

    const int tid = threadIdx.x;
    const int tx = tid & 15, ty = tid >> 4;
    const int row0 = blockIdx.y * 128;
    const int col0 = blockIdx.x * 128;

    // per-thread tile-load coordinates (2 chunks of the 512 float4 loads)
    int m_[2], kc_[2];
#pragma unroll
    for (int l = 0; l < 2; l++) {
        int f4 = tid + (l << 8);
        m_[l]  = f4 >> 2;
        kc_[l] = (f4 & 3) << 2;
    }

    float acc[8][8];
#pragma unroll
    for (int i = 0; i < 8; i++)
#pragma unroll
        for (int j = 0; j < 8; j++) acc[i][j] = 0.f;

    float4 ra[2], rb[2];
    // prologue: load k0 = 0 tile
#pragma unroll
    for (int l = 0; l < 2; l++) {
        ra[l] = *(const float4*)(&g_xr[row0 + m_[l]][kc_[l]]);
        rb[l] = *(const float4*)(W + (size_t)(col0 + m_[l]) * Dz + kc_[l]);
    }
#pragma unroll
    for (int l = 0; l < 2; l++) {
        As[kc_[l] + 0][m_[l]] = ra[l].x; As[kc_[l] + 1][m_[l]] = ra[l].y;
        As[kc_[l] + 2][m_[l]] = ra[l].z; As[kc_[l] + 3][m_[l]] = ra[l].w;
        Bs[kc_[l] + 0][m_[l]] = rb[l].x; Bs[kc_[l] + 1][m_[l]] = rb[l].y;
        Bs[kc_[l] + 2][m_[l]] = rb[l].z; Bs[kc_[l] + 3][m_[l]] = rb[l].w;
    }
    __syncthreads();

    for (int k0 = 0; k0 < Dz; k0 += 16) {
        const bool more = (k0 + 16) < Dz;
        if (more) {
#pragma unroll
            for (int l = 0; l < 2; l++) {
                ra[l] = *(const float4*)(&g_xr[row0 + m_[l]][k0 + 16 + kc_[l]]);
                rb[l] = *(const float4*)(W + (size_t)(col0 + m_[l]) * Dz + k0 + 16 + kc_[l]);
            }
        }
#pragma unroll
        for (int kk = 0; kk < 16; kk++) {
            float a[8], w[8];
            *(float4*)(a)     = *(const float4*)&As[kk][ty * 8];
            *(float4*)(a + 4) = *(const float4*)&As[kk][ty * 8 + 4];
            *(float4*)(w)     = *(const float4*)&Bs[kk][tx * 8];
            *(float4*)(w + 4) = *(const float4*)&Bs[kk][tx * 8 + 4];
#pragma unroll
            for (int i = 0; i < 8; i++)
#pragma unroll
                for (int j = 0; j < 8; j++) acc[i][j] += a[i] * w[j];
        }
        __syncthreads();
        if (more) {
#pragma unroll
            for (int l = 0; l < 2; l++) {
                As[kc_[l] + 0][m_[l]] = ra[l].x; As[kc_[l] + 1][m_[l]] = ra[l].y;
                As[kc_[l] + 2][m_[l]] = ra[l].z; As[kc_[l] + 3][m_[l]] = ra[l].w;
                Bs[kc_[l] + 0][m_[l]] = rb[l].x; Bs[kc_[l] + 1][m_[l]] = rb[l].y;
                Bs[kc_[l] + 2][m_[l]] = rb[l].z; Bs[kc_[l] + 3][m_[l]] = rb[l].w;
            }
            __syncthreads();
        }
    }

    float4 bia = *(const float4*)(bias + col0 + tx * 8);
    float4 bib = *(const float4*)(bias + col0 + tx * 8 + 4);
    float* outp = &g_pre[0][0][0][0] + (size_t)dir * Tz * Bz * Gz;
#pragma unroll
    for (int i = 0; i < 8; i++) {
        int r = row0 + ty * 8 + i;
        float* op = outp + (size_t)r * Gz + col0 + tx * 8;
        *(float4*)(op)     = make_float4(acc[i][0] + bia.x, acc[i][1] + bia.y, acc[i][2] + bia.z, acc[i][3] + bia.w);
        *(float4*)(op + 4) = make_float4(acc[i][4] + bib.x, acc[i][5] + bib.y, acc[i][6] + bib.z, acc[i][7] + bib.w);
    }
}

// ---------------- persistent LSTM: full-chip, per-dir grid sync per step ----------------
// CTA = (dir, j-slice of 4 hidden units). W_hh slice (16 rows x 256) in smem as float2
// pairs: ws2[gr2][k] = (W[row 2*gr2][k], W[row 2*gr2+1][k]). Thread = (kq, gr2, bq):
// 2 gate-rows x 4 batches x 64 k -> 16 FFMA per (LDS.128 + LDS.64).
#define WS2_STRIDE 258   // float2 units, padded: rows 4 banks apart -> conflict-free
#define SMEM_FLOATS (8*WS2_STRIDE*2 + 256*32 + 3*16*32 + 16*32 + 32)

__global__ __launch_bounds__(256) void lstm_persist(
    const float* __restrict__ Whf, const float* __restrict__ Whb,
    const int* __restrict__ lengths)
{
    extern __shared__ float smem[];
    float2* ws2 = (float2*)smem;                    // [8][258]
    float*  hs  = smem + 8 * WS2_STRIDE * 2;        // [256][32]
    float*  red = hs + 256 * 32;                    // [3][16][32]
    float*  act = red + 3 * 16 * 32;                // [16][32]
    int*    ls  = (int*)(act + 16 * 32);            // [32]

    const int cta = blockIdx.x;
    const int dir = cta >> 6;
    const int jc  = cta & 63;
    const int j0  = jc * JP;
    const int tid = threadIdx.x;

    const float* __restrict__ W = dir ? Whb : Whf;
    // ws2[gr2][k] = (W_hh[grow(2*gr2)][k], W_hh[grow(2*gr2+1)][k]); grow(gr)=(gr>>2)*Hz+j0+(gr&3)
    for (int i = tid; i < 8 * Hz; i += 256) {
        int g2 = i >> 8;
        int k  = i & 255;
        int gr0 = 2 * g2, gr1 = gr0 + 1;
        int grow0 = (gr0 >> 2) * Hz + j0 + (gr0 & 3);
        int grow1 = (gr1 >> 2) * Hz + j0 + (gr1 & 3);
        ws2[g2 * WS2_STRIDE + k] = make_float2(W[(size_t)grow0 * Hz + k], W[(size_t)grow1 * Hz + k]);
    }
    if (tid < 32) ls[tid] = lengths[tid];
    __syncthreads();

    // GEMV role: kq = k-quarter, gr2 = gate-row pair, bq = batch quad
    const int kq  = tid >> 6;          // 0..3
    const int gr2 = (tid >> 3) & 7;    // 0..7
    const int bq  = tid & 7;           // 0..7
    const int gr0 = 2 * gr2, gr1 = gr0 + 1;
    const float2* w2   = ws2 + gr2 * WS2_STRIDE;
    const float*  hrow = hs + bq * 4;
    const float* __restrict__ preb = &g_pre[0][0][0][0] + (size_t)dir * Tz * Bz * Gz;

    // activation role (tid < 128): jj = tid>>5, b = tid&31
    float c = 0.f;
    const int a_jj = tid >> 5;
    const int a_b  = tid & 31;
    const int a_len = (tid < 128) ? ls[a_b] : 0;

    unsigned* syncp = &g_sync[dir][0];

    int par = 0;
    for (int t = 0; t < Tz; t++) {
        // stage h broadcast buffer (32 KB) into smem
        {
            const float4* hsrc = (const float4*)(&g_hT[par][dir][0][0]);
            float4* hdst = (float4*)hs;
#pragma unroll
            for (int i = 0; i < 8; i++)
                hdst[tid + i * 256] = hsrc[tid + i * 256];
        }
        // preload pre-activations (kq==0 threads): 2 gate-rows x 4 batches
        float p[2][4];
        if (kq == 0) {
            int grow0g = (gr0 >> 2) * Hz + j0 + (gr0 & 3);
            int grow1g = (gr1 >> 2) * Hz + j0 + (gr1 & 3);
            int b0 = bq * 4;
#pragma unroll
            for (int q = 0; q < 4; q++) {
                int lb = ls[b0 + q];
                int ti = (dir && t < lb) ? (lb - 1 - t) : t;
                const float* pr = preb + ((size_t)ti * Bz + b0 + q) * Gz;
                p[0][q] = pr[grow0g];
                p[1][q] = pr[grow1g];
            }
        }
        __syncthreads();

        // GEMV: 8 accumulators (2 rows x 4 batches) over 64 k
        float a00 = 0.f, a01 = 0.f, a02 = 0.f, a03 = 0.f;
        float a10 = 0.f, a11 = 0.f, a12 = 0.f, a13 = 0.f;
        const int kbase = kq * 64;
#pragma unroll 8
        for (int k = kbase; k < kbase + 64; k++) {
            float2 w = w2[k];
            float4 h4 = *(const float4*)(hrow + k * 32);
            a00 += w.x * h4.x; a01 += w.x * h4.y; a02 += w.x * h4.z; a03 += w.x * h4.w;
            a10 += w.y * h4.x; a11 += w.y * h4.y; a12 += w.y * h4.z; a13 += w.y * h4.w;
        }
        if (kq > 0) {
            float* r0 = &red[((kq - 1) * 16 + gr0) * 32 + bq * 4];
            float* r1 = &red[((kq - 1) * 16 + gr1) * 32 + bq * 4];
            *(float4*)r0 = make_float4(a00, a01, a02, a03);
            *(float4*)r1 = make_float4(a10, a11, a12, a13);
        }
        __syncthreads();
        if (kq == 0) {
            float4 s0 = make_float4(a00 + p[0][0], a01 + p[0][1], a02 + p[0][2], a03 + p[0][3]);
            float4 s1 = make_float4(a10 + p[1][0], a11 + p[1][1], a12 + p[1][2], a13 + p[1][3]);
#pragma unroll
            for (int q = 0; q < 3; q++) {
                float4 r0 = *(const float4*)&red[(q * 16 + gr0) * 32 + bq * 4];
                float4 r1 = *(const float4*)&red[(q * 16 + gr1) * 32 + bq * 4];
                s0.x += r0.x; s0.y += r0.y; s0.z += r0.z; s0.w += r0.w;
                s1.x += r1.x; s1.y += r1.y; s1.z += r1.z; s1.w += r1.w;
            }
            *(float4*)&act[gr0 * 32 + bq * 4] = s0;
            *(float4*)&act[gr1 * 32 + bq * 4] = s1;
        }
        __syncthreads();

        // activations + state update + publish (threads 0..127)
        if (tid < 128) {
            float gi = act[(0  + a_jj) * 32 + a_b];
            float gf = act[(4  + a_jj) * 32 + a_b];
            float gg = act[(8  + a_jj) * 32 + a_b];
            float go = act[(12 + a_jj) * 32 + a_b];
            c = sigm(gf) * c + sigm(gi) * tanhf(gg);
            float hv = sigm(go) * tanhf(c);
            g_hT[par ^ 1][dir][j0 + a_jj][a_b] = hv;
            int ti = (dir && t < a_len) ? (a_len - 1 - t) : t;
            g_h[dir][a_b][ti][j0 + a_jj] = hv;
        }
        __threadfence();
        __syncthreads();
        if (tid == 0) {
            atomicAdd(&syncp[t], 1u);
            while (*(volatile unsigned*)&syncp[t] < 64u) __nanosleep(64);
        }
        __syncthreads();
        par ^= 1;
    }
}

// ---------------- emissions: em[b][t][k] = hcat . WclfT[:,k] + b_clf[k] ----------------
__global__ __launch_bounds__(256) void emis_kernel(const float* __restrict__ b_clf)
{
    int gw = (blockIdx.x * blockDim.x + threadIdx.x) >> 5;   // b*512+t
    int lane = threadIdx.x & 31;
    int b = gw >> 9, t = gw & 511;

    float acc = b_clf[lane];
#pragma unroll
    for (int half = 0; half < 2; half++) {
        const float* hb = &g_h[half][b][t][0];
        for (int j0 = 0; j0 < Hz; j0 += 32) {
            float hv = hb[j0 + lane];
#pragma unroll
            for (int jj = 0; jj < 32; jj++) {
                float hj = __shfl_sync(0xffffffffu, hv, jj);
                acc += hj * g_WclfT[half * Hz + j0 + jj][lane];
            }
        }
    }
    g_em[b][t][lane] = acc;
}

// ---------------- CRF NLL: one warp per batch ----------------
__global__ __launch_bounds__(32) void crf_nll_kernel(
    const int* __restrict__ lengths, const int* __restrict__ targets,
    const float* __restrict__ start_t, const float* __restrict__ end_t,
    const float* __restrict__ trans)
{
    const int b = blockIdx.x;
    const int lane = threadIdx.x;
    __shared__ float alpha_s[32];

    float tc[32];
#pragma unroll
    for (int k = 0; k < 32; k++) tc[k] = trans[k * Kz + lane];

    const int len = lengths[b];
    const int* tgt = targets + (size_t)b * Tz;
    const float* em = &g_em[b][0][0];

    float part = 0.f;
    for (int t = lane; t < Tz; t += 32) {
        int tg = tgt[t];
        if (t == 0) {
            part += start_t[tg] + em[tg];
        } else if (t < len) {
            int tp = tgt[t - 1];
            part += trans[tp * Kz + tg] + em[t * Kz + tg];
        }
    }
#pragma unroll
    for (int off = 16; off >= 1; off >>= 1)
        part += __shfl_xor_sync(0xffffffffu, part, off);
    part += end_t[tgt[len - 1]];

    float alpha = start_t[lane] + em[lane];
    for (int t = 1; t < len; t++) {
        alpha_s[lane] = alpha;
        __syncwarp();
        float m = -3.0e38f;
#pragma unroll
        for (int k = 0; k < 32; k++) m = fmaxf(m, alpha_s[k] + tc[k]);
        float s = 0.f;
#pragma unroll
        for (int k = 0; k < 32; k++) s += __expf(alpha_s[k] + tc[k] - m);
        alpha = m + __logf(s) + em[t * Kz + lane];
        __syncwarp();
    }
    float v = alpha + end_t[lane];
    float M = v;
#pragma unroll
    for (int off = 16; off >= 1; off >>= 1)
        M = fmaxf(M, __shfl_xor_sync(0xffffffffu, M, off));
    float S = __expf(v - M);
#pragma unroll
    for (int off = 16; off >= 1; off >>= 1)
        S += __shfl_xor_sync(0xffffffffu, S, off);
    float logZ = M + __logf(S);

    if (lane == 0) g_partial[b] = part - logZ;
}

__global__ __launch_bounds__(32) void finalize_kernel(float* __restrict__ out)
{
    int lane = threadIdx.x;
    float p = g_partial[lane];
#pragma unroll
    for (int off = 16; off >= 1; off >>= 1)
        p += __shfl_xor_sync(0xffffffffu, p, off);
    if (lane == 0) out[0] = -p / (float)Bz;
}

// ---------------- Viterbi: one warp per batch ----------------
__global__ __launch_bounds__(32) void viterbi_kernel(
    const int* __restrict__ lengths,
    const float* __restrict__ start_t, const float* __restrict__ end_t,
    const float* __restrict__ trans, float* __restrict__ out)
{
    const int b = blockIdx.x;
    const int lane = threadIdx.x;
    __shared__ float score_s[32];
    __shared__ uint8_t hist[Tz - 1][32];
    __shared__ int last_sh;

    float tc[32];
#pragma unroll
    for (int k = 0; k < 32; k++) tc[k] = trans[k * Kz + lane];

    const int len = lengths[b];
    const float* em = &g_em[b][0][0];

    float score = start_t[lane] + em[lane];
    for (int t = 1; t < len; t++) {
        score_s[lane] = score;
        __syncwarp();
        float best = -3.0e38f;
        int bi = 0;
#pragma unroll
        for (int k = 0; k < 32; k++) {
            float v = score_s[k] + tc[k];
            if (v > best) { best = v; bi = k; }   // strict >: first-index tiebreak
        }
        score = best + em[t * Kz + lane];
        hist[t - 1][lane] = (uint8_t)bi;
        __syncwarp();
    }

    score_s[lane] = score + end_t[lane];
    __syncwarp();
    if (lane == 0) {
        float best = -3.0e38f;
        int bi = 0;
#pragma unroll
        for (int k = 0; k < 32; k++) {
            if (score_s[k] > best) { best = score_s[k]; bi = k; }
        }
        last_sh = bi;
    }
    __syncwarp();

    if (lane == 0) {
        float* op = out + 1 + (size_t)b * Tz;
        int cur = last_sh;
        for (int t = Tz - 1; t >= 1; t--) {
            op[t] = (t < len) ? (float)cur : 0.0f;
            if (t < len) cur = (int)hist[t - 1][cur];
        }
        op[0] = (float)cur;
    }
}

// ---------------- launch ----------------
extern "C" void kernel_launch(void* const* d_in, const int* in_sizes, int n_in,
                              void* d_out, int out_size)
{
    const float* x       = (const float*)d_in[0];
    const int*   lengths = (const int*)  d_in[1];
    const int*   targets = (const int*)  d_in[3];
    const float* W_ih_f  = (const float*)d_in[4];
    const float* W_hh_f  = (const float*)d_in[5];
    const float* b_f     = (const float*)d_in[6];
    const float* W_ih_b  = (const float*)d_in[7];
    const float* W_hh_b  = (const float*)d_in[8];
    const float* b_b     = (const float*)d_in[9];
    const float* W_clf   = (const float*)d_in[10];
    const float* b_clf   = (const float*)d_in[11];
    const float* start_t = (const float*)d_in[12];
    const float* end_t   = (const float*)d_in[13];
    const float* trans   = (const float*)d_in[14];
    float* out = (float*)d_out;

    // reset per-launch state (graph-replay safe)
    void* psync = nullptr; void* phT = nullptr;
    cudaGetSymbolAddress(&psync, g_sync);
    cudaGetSymbolAddress(&phT, g_hT);
    cudaMemsetAsync(psync, 0, sizeof(unsigned) * 2 * Tz);
    cudaMemsetAsync(phT, 0, sizeof(float) * 2 * 2 * Hz * Bz);

    prep_kernel<<<64, 256>>>(W_clf);
    xr_kernel<<<Tz * Bz, 192>>>(x);

    dim3 ggrid(Gz / 128, (Tz * Bz) / 128, 2);
    gemm_pre_kernel<<<ggrid, 256>>>(W_ih_f, W_ih_b, b_f, b_b);

    cudaFuncSetAttribute(lstm_persist, cudaFuncAttributeMaxDynamicSharedMemorySize,
                         SMEM_FLOATS * (int)sizeof(float));
    lstm_persist<<<NCTA, 256, SMEM_FLOATS * sizeof(float)>>>(W_hh_f, W_hh_b, lengths);

    emis_kernel<<<(Bz * Tz) / 8, 256>>>(b_clf);

    crf_nll_kernel<<<Bz, 32>>>(lengths, targets, start_t, end_t, trans);
    finalize_kernel<<<1, 32>>>(out);
    viterbi_kernel<<<Bz, 32>>>(lengths, start_t, end_t, trans, out);
}

// round 8
// speedup vs baseline: 4.7890x; 1.0271x over previous
#include <cuda_runtime.h>
#include <math.h>
#include <stdint.h>

#define Bz 32
#define Tz 512
#define Dz 768
#define Hz 256
#define Gz 1024   // 4*Hz
#define Kz 32
#define NCTA 128  // persistent LSTM CTAs (2 dirs x 64 j-slices)
#define JP 4      // hidden units per CTA
#define HB 16     // batches per half-CTA chain

// ---------------- scratch (device globals; no allocation allowed) ----------------
__device__ float  g_pre[2][Tz][Bz][Gz];     // pre-activations (134 MB)
__device__ float  g_h[2][Bz][Tz][Hz];       // hidden states at OUTPUT positions (33 MB)
__device__ float  g_em[Bz][Tz][Kz];         // emissions (2 MB)
__device__ float  g_WclfT[2 * Hz][Kz];      // W_clf transposed
__device__ float  g_partial[Bz];            // per-batch (num - logZ)
__device__ float  g_xr[Tz * Bz][Dz];        // x re-laid-out: row r = t*32+b (50 MB)
__device__ float  g_hT2[2][2][2][Hz][HB];   // h ping-pong: [parity][dir][half][k][bl]
__device__ unsigned g_syncH[2][2][Tz];      // per-(dir,half) per-step arrival counters

__device__ __forceinline__ float sigm(float x) { return 1.0f / (1.0f + expf(-x)); }

// ---------------- prep: W_clf transpose ----------------
__global__ void prep_kernel(const float* __restrict__ Wclf) {
    int r = blockIdx.x * blockDim.x + threadIdx.x;
    if (r < 2 * Hz * Kz) {
        int j = r / Kz, k = r % Kz;
        g_WclfT[j][k] = Wclf[(size_t)k * (2 * Hz) + j];
    }
}

// ---------------- x relayout: xr[t*32+b][d] = x[b][t][d] ----------------
__global__ __launch_bounds__(192) void xr_kernel(const float* __restrict__ x) {
    int r = blockIdx.x;                 // 0..16383
    int b = r & 31, t = r >> 5;
    const float4* src = (const float4*)(x + ((size_t)b * Tz + t) * Dz);
    float4* dst = (float4*)(&g_xr[r][0]);
    dst[threadIdx.x] = src[threadIdx.x];
}

// ---------------- input GEMM (software-pipelined): pre = xr . W_ih^T + bias ----
__global__ __launch_bounds__(256) void gemm_pre_kernel(
    const float* __restrict__ Wf, const float* __restrict__ Wb,
    const float* __restrict__ bf, const float* __restrict__ bb)
{
    const int dir = blockIdx.z;
    const float* __restrict__ W    = dir ? Wb : Wf;
    const float* __restrict__ bias = dir ? bb : bf;

    __shared__ float As[16][132];
    __shared__ float Bs[16][132];

    const int tid = threadIdx.x;
    const int tx = tid & 15, ty = tid >> 4;
    const int row0 = blockIdx.y * 128;
    const int col0 = blockIdx.x * 128;

    int m_[2], kc_[2];
#pragma unroll
    for (int l = 0; l < 2; l++) {
        int f4 = tid + (l << 8);
        m_[l]  = f4 >> 2;
        kc_[l] = (f4 & 3) << 2;
    }

    float acc[8][8];
#pragma unroll
    for (int i = 0; i < 8; i++)
#pragma unroll
        for (int j = 0; j < 8; j++) acc[i][j] = 0.f;

    float4 ra[2], rb[2];
#pragma unroll
    for (int l = 0; l < 2; l++) {
        ra[l] = *(const float4*)(&g_xr[row0 + m_[l]][kc_[l]]);
        rb[l] = *(const float4*)(W + (size_t)(col0 + m_[l]) * Dz + kc_[l]);
    }
#pragma unroll
    for (int l = 0; l < 2; l++) {
        As[kc_[l] + 0][m_[l]] = ra[l].x; As[kc_[l] + 1][m_[l]] = ra[l].y;
        As[kc_[l] + 2][m_[l]] = ra[l].z; As[kc_[l] + 3][m_[l]] = ra[l].w;
        Bs[kc_[l] + 0][m_[l]] = rb[l].x; Bs[kc_[l] + 1][m_[l]] = rb[l].y;
        Bs[kc_[l] + 2][m_[l]] = rb[l].z; Bs[kc_[l] + 3][m_[l]] = rb[l].w;
    }
    __syncthreads();

    for (int k0 = 0; k0 < Dz; k0 += 16) {
        const bool more = (k0 + 16) < Dz;
        if (more) {
#pragma unroll
            for (int l = 0; l < 2; l++) {
                ra[l] = *(const float4*)(&g_xr[row0 + m_[l]][k0 + 16 + kc_[l]]);
                rb[l] = *(const float4*)(W + (size_t)(col0 + m_[l]) * Dz + k0 + 16 + kc_[l]);
            }
        }
#pragma unroll
        for (int kk = 0; kk < 16; kk++) {
            float a[8], w[8];
            *(float4*)(a)     = *(const float4*)&As[kk][ty * 8];
            *(float4*)(a + 4) = *(const float4*)&As[kk][ty * 8 + 4];
            *(float4*)(w)     = *(const float4*)&Bs[kk][tx * 8];
            *(float4*)(w + 4) = *(const float4*)&Bs[kk][tx * 8 + 4];
#pragma unroll
            for (int i = 0; i < 8; i++)
#pragma unroll
                for (int j = 0; j < 8; j++) acc[i][j] += a[i] * w[j];
        }
        __syncthreads();
        if (more) {
#pragma unroll
            for (int l = 0; l < 2; l++) {
                As[kc_[l] + 0][m_[l]] = ra[l].x; As[kc_[l] + 1][m_[l]] = ra[l].y;
                As[kc_[l] + 2][m_[l]] = ra[l].z; As[kc_[l] + 3][m_[l]] = ra[l].w;
                Bs[kc_[l] + 0][m_[l]] = rb[l].x; Bs[kc_[l] + 1][m_[l]] = rb[l].y;
                Bs[kc_[l] + 2][m_[l]] = rb[l].z; Bs[kc_[l] + 3][m_[l]] = rb[l].w;
            }
            __syncthreads();
        }
    }

    float4 bia = *(const float4*)(bias + col0 + tx * 8);
    float4 bib = *(const float4*)(bias + col0 + tx * 8 + 4);
    float* outp = &g_pre[0][0][0][0] + (size_t)dir * Tz * Bz * Gz;
#pragma unroll
    for (int i = 0; i < 8; i++) {
        int r = row0 + ty * 8 + i;
        float* op = outp + (size_t)r * Gz + col0 + tx * 8;
        *(float4*)(op)     = make_float4(acc[i][0] + bia.x, acc[i][1] + bia.y, acc[i][2] + bia.z, acc[i][3] + bia.w);
        *(float4*)(op + 4) = make_float4(acc[i][4] + bib.x, acc[i][5] + bib.y, acc[i][6] + bib.z, acc[i][7] + bib.w);
    }
}

// ---------------- persistent LSTM: two independent batch-half chains per CTA ----------------
// CTA = (dir, j-slice of 4 hidden units). Threads 0-127 = batches 0-15, 128-255 = 16-31.
// Each half: own named barrier, own ping-pong global buffer, own 64-CTA counter.
// Sync latency of one half overlaps with the other half's GEMV on the same SMSPs.
#define WS2_STRIDE 258   // float2 units, rows 4 banks apart -> conflict-free
#define SMEM_FLOATS (8*WS2_STRIDE*2 + 2*256*HB + 2*3*16*HB + 2*16*HB + 32)

__global__ __launch_bounds__(256) void lstm_persist(
    const float* __restrict__ Whf, const float* __restrict__ Whb,
    const int* __restrict__ lengths)
{
    extern __shared__ float smem[];
    float2* ws2 = (float2*)smem;                      // [8][258] float2 (shared by halves)
    float*  hs  = smem + 8 * WS2_STRIDE * 2;          // [2][256][HB]
    float*  red = hs + 2 * 256 * HB;                  // [2][3][16][HB]
    float*  act = red + 2 * 3 * 16 * HB;              // [2][16][HB]
    int*    ls  = (int*)(act + 2 * 16 * HB);          // [32]

    const int cta = blockIdx.x;
    const int dir = cta >> 6;
    const int j0  = (cta & 63) * JP;
    const int tid = threadIdx.x;
    const int half = tid >> 7;
    const int th   = tid & 127;

    const float* __restrict__ W = dir ? Whb : Whf;
    for (int i = tid; i < 8 * Hz; i += 256) {
        int g2 = i >> 8;
        int k  = i & 255;
        int gr0i = 2 * g2, gr1i = gr0i + 1;
        int grow0 = (gr0i >> 2) * Hz + j0 + (gr0i & 3);
        int grow1 = (gr1i >> 2) * Hz + j0 + (gr1i & 3);
        ws2[g2 * WS2_STRIDE + k] = make_float2(W[(size_t)grow0 * Hz + k], W[(size_t)grow1 * Hz + k]);
    }
    if (tid < 32) ls[tid] = lengths[tid];
    __syncthreads();

    // GEMV role within half: kq = k-quarter, gr2 = gate-row pair, bq = batch quad (of HB=16)
    const int kq  = th >> 5;           // 0..3
    const int gr2 = (th >> 2) & 7;     // 0..7
    const int bq  = th & 3;            // 0..3
    const int gr0 = 2 * gr2, gr1 = gr0 + 1;
    const float2* w2   = ws2 + gr2 * WS2_STRIDE;
    float* hsh = hs + half * (256 * HB);
    const float*  hrow = hsh + bq * 4;
    float* redh = red + half * (3 * 16 * HB);
    float* acth = act + half * (16 * HB);
    const float* __restrict__ preb = &g_pre[0][0][0][0] + (size_t)dir * Tz * Bz * Gz;

    // activation role (th < 64): a_jj = th>>4, local batch = th&15
    float c = 0.f;
    const int a_jj = th >> 4;
    const int a_bl = th & 15;
    const int a_b  = half * HB + a_bl;
    const int a_len = (th < 64) ? ls[a_b] : 0;

    unsigned* syncp = &g_syncH[dir][half][0];
    const int barid = half + 1;

    int par = 0;
    for (int t = 0; t < Tz; t++) {
        // stage this half's h (16 KB) from global ping-pong, L2-direct
        {
            const float4* hsrc = (const float4*)(&g_hT2[par][dir][half][0][0]);
            float4* hdst = (float4*)hsh;
#pragma unroll
            for (int i = 0; i < 8; i++)
                hdst[th + i * 128] = __ldcg(hsrc + th + i * 128);
        }
        // preload pre-activations (kq==0 threads): 2 gate-rows x 4 batches
        float p[2][4];
        if (kq == 0) {
            int grow0g = (gr0 >> 2) * Hz + j0 + (gr0 & 3);
            int grow1g = (gr1 >> 2) * Hz + j0 + (gr1 & 3);
            int b0 = half * HB + bq * 4;
#pragma unroll
            for (int q = 0; q < 4; q++) {
                int lb = ls[b0 + q];
                int ti = (dir && t < lb) ? (lb - 1 - t) : t;
                const float* pr = preb + ((size_t)ti * Bz + b0 + q) * Gz;
                p[0][q] = pr[grow0g];
                p[1][q] = pr[grow1g];
            }
        }
        asm volatile("bar.sync %0, 128;" :: "r"(barid) : "memory");

        // GEMV: 8 accumulators (2 rows x 4 batches) over 64 k
        float a00 = 0.f, a01 = 0.f, a02 = 0.f, a03 = 0.f;
        float a10 = 0.f, a11 = 0.f, a12 = 0.f, a13 = 0.f;
        const int kbase = kq * 64;
#pragma unroll 8
        for (int k = kbase; k < kbase + 64; k++) {
            float2 w = w2[k];
            float4 h4 = *(const float4*)(hrow + k * HB);
            a00 += w.x * h4.x; a01 += w.x * h4.y; a02 += w.x * h4.z; a03 += w.x * h4.w;
            a10 += w.y * h4.x; a11 += w.y * h4.y; a12 += w.y * h4.z; a13 += w.y * h4.w;
        }
        if (kq > 0) {
            *(float4*)&redh[((kq - 1) * 16 + gr0) * HB + bq * 4] = make_float4(a00, a01, a02, a03);
            *(float4*)&redh[((kq - 1) * 16 + gr1) * HB + bq * 4] = make_float4(a10, a11, a12, a13);
        }
        asm volatile("bar.sync %0, 128;" :: "r"(barid) : "memory");
        if (kq == 0) {
            float4 s0 = make_float4(a00 + p[0][0], a01 + p[0][1], a02 + p[0][2], a03 + p[0][3]);
            float4 s1 = make_float4(a10 + p[1][0], a11 + p[1][1], a12 + p[1][2], a13 + p[1][3]);
#pragma unroll
            for (int q = 0; q < 3; q++) {
                float4 r0 = *(const float4*)&redh[(q * 16 + gr0) * HB + bq * 4];
                float4 r1 = *(const float4*)&redh[(q * 16 + gr1) * HB + bq * 4];
                s0.x += r0.x; s0.y += r0.y; s0.z += r0.z; s0.w += r0.w;
                s1.x += r1.x; s1.y += r1.y; s1.z += r1.z; s1.w += r1.w;
            }
            *(float4*)&acth[gr0 * HB + bq * 4] = s0;
            *(float4*)&acth[gr1 * HB + bq * 4] = s1;
        }
        asm volatile("bar.sync %0, 128;" :: "r"(barid) : "memory");

        // activations + state update + publish (threads th < 64 of each half)
        if (th < 64) {
            float gi = acth[(0  + a_jj) * HB + a_bl];
            float gf = acth[(4  + a_jj) * HB + a_bl];
            float gg = acth[(8  + a_jj) * HB + a_bl];
            float go = acth[(12 + a_jj) * HB + a_bl];
            c = sigm(gf) * c + sigm(gi) * tanhf(gg);
            float hv = sigm(go) * tanhf(c);
            __stcg(&g_hT2[par ^ 1][dir][half][j0 + a_jj][a_bl], hv);
            int ti = (dir && t < a_len) ? (a_len - 1 - t) : t;
            g_h[dir][a_b][ti][j0 + a_jj] = hv;
            __threadfence();   // only 2 warps per half; other half's warps keep computing
        }
        asm volatile("bar.sync %0, 128;" :: "r"(barid) : "memory");
        if (th == 0) {
            unsigned* cp = &syncp[t];
            atomicAdd(cp, 1u);
            unsigned v;
            do {
                asm volatile("ld.acquire.gpu.global.u32 %0, [%1];" : "=r"(v) : "l"(cp));
                if (v >= 64u) break;
                __nanosleep(32);
            } while (true);
        }
        asm volatile("bar.sync %0, 128;" :: "r"(barid) : "memory");
        par ^= 1;
    }
}

// ---------------- emissions: em[b][t][k] = hcat . WclfT[:,k] + b_clf[k] ----------------
__global__ __launch_bounds__(256) void emis_kernel(const float* __restrict__ b_clf)
{
    int gw = (blockIdx.x * blockDim.x + threadIdx.x) >> 5;   // b*512+t
    int lane = threadIdx.x & 31;
    int b = gw >> 9, t = gw & 511;

    float acc = b_clf[lane];
#pragma unroll
    for (int half = 0; half < 2; half++) {
        const float* hb = &g_h[half][b][t][0];
        for (int j0 = 0; j0 < Hz; j0 += 32) {
            float hv = hb[j0 + lane];
#pragma unroll
            for (int jj = 0; jj < 32; jj++) {
                float hj = __shfl_sync(0xffffffffu, hv, jj);
                acc += hj * g_WclfT[half * Hz + j0 + jj][lane];
            }
        }
    }
    g_em[b][t][lane] = acc;
}

// ---------------- fused tail: blocks 0-31 = viterbi, 32-63 = CRF NLL ----------------
__global__ __launch_bounds__(32) void tail_kernel(
    const int* __restrict__ lengths, const int* __restrict__ targets,
    const float* __restrict__ start_t, const float* __restrict__ end_t,
    const float* __restrict__ trans, float* __restrict__ out)
{
    const int lane = threadIdx.x;
    __shared__ float sh32[32];
    __shared__ uint8_t hist[Tz - 1][32];
    __shared__ int last_sh;

    float tc[32];
#pragma unroll
    for (int k = 0; k < 32; k++) tc[k] = trans[k * Kz + lane];

    if (blockIdx.x >= 32) {
        // ---- CRF NLL for batch b ----
        const int b = blockIdx.x - 32;
        const int len = lengths[b];
        const int* tgt = targets + (size_t)b * Tz;
        const float* em = &g_em[b][0][0];

        float part = 0.f;
        for (int t = lane; t < Tz; t += 32) {
            int tg = tgt[t];
            if (t == 0) {
                part += start_t[tg] + em[tg];
            } else if (t < len) {
                int tp = tgt[t - 1];
                part += trans[tp * Kz + tg] + em[t * Kz + tg];
            }
        }
#pragma unroll
        for (int off = 16; off >= 1; off >>= 1)
            part += __shfl_xor_sync(0xffffffffu, part, off);
        part += end_t[tgt[len - 1]];

        float alpha = start_t[lane] + em[lane];
        for (int t = 1; t < len; t++) {
            sh32[lane] = alpha;
            __syncwarp();
            float m = -3.0e38f;
#pragma unroll
            for (int k = 0; k < 32; k++) m = fmaxf(m, sh32[k] + tc[k]);
            float s = 0.f;
#pragma unroll
            for (int k = 0; k < 32; k++) s += __expf(sh32[k] + tc[k] - m);
            alpha = m + __logf(s) + em[t * Kz + lane];
            __syncwarp();
        }
        float v = alpha + end_t[lane];
        float M = v;
#pragma unroll
        for (int off = 16; off >= 1; off >>= 1)
            M = fmaxf(M, __shfl_xor_sync(0xffffffffu, M, off));
        float S = __expf(v - M);
#pragma unroll
        for (int off = 16; off >= 1; off >>= 1)
            S += __shfl_xor_sync(0xffffffffu, S, off);
        float logZ = M + __logf(S);

        if (lane == 0) g_partial[b] = part - logZ;
        return;
    }

    // ---- Viterbi for batch b ----
    const int b = blockIdx.x;
    const int len = lengths[b];
    const float* em = &g_em[b][0][0];

    float score = start_t[lane] + em[lane];
    for (int t = 1; t < len; t++) {
        sh32[lane] = score;
        __syncwarp();
        float best = -3.0e38f;
        int bi = 0;
#pragma unroll
        for (int k = 0; k < 32; k++) {
            float v = sh32[k] + tc[k];
            if (v > best) { best = v; bi = k; }   // strict >: first-index tiebreak
        }
        score = best + em[t * Kz + lane];
        hist[t - 1][lane] = (uint8_t)bi;
        __syncwarp();
    }

    sh32[lane] = score + end_t[lane];
    __syncwarp();
    if (lane == 0) {
        float best = -3.0e38f;
        int bi = 0;
#pragma unroll
        for (int k = 0; k < 32; k++) {
            if (sh32[k] > best) { best = sh32[k]; bi = k; }
        }
        last_sh = bi;
    }
    __syncwarp();

    if (lane == 0) {
        float* op = out + 1 + (size_t)b * Tz;
        int cur = last_sh;
        for (int t = Tz - 1; t >= 1; t--) {
            op[t] = (t < len) ? (float)cur : 0.0f;
            if (t < len) cur = (int)hist[t - 1][cur];
        }
        op[0] = (float)cur;
    }
}

__global__ __launch_bounds__(32) void finalize_kernel(float* __restrict__ out)
{
    int lane = threadIdx.x;
    float p = g_partial[lane];
#pragma unroll
    for (int off = 16; off >= 1; off >>= 1)
        p += __shfl_xor_sync(0xffffffffu, p, off);
    if (lane == 0) out[0] = -p / (float)Bz;
}

// ---------------- launch ----------------
extern "C" void kernel_launch(void* const* d_in, const int* in_sizes, int n_in,
                              void* d_out, int out_size)
{
    const float* x       = (const float*)d_in[0];
    const int*   lengths = (const int*)  d_in[1];
    const int*   targets = (const int*)  d_in[3];
    const float* W_ih_f  = (const float*)d_in[4];
    const float* W_hh_f  = (const float*)d_in[5];
    const float* b_f     = (const float*)d_in[6];
    const float* W_ih_b  = (const float*)d_in[7];
    const float* W_hh_b  = (const float*)d_in[8];
    const float* b_b     = (const float*)d_in[9];
    const float* W_clf   = (const float*)d_in[10];
    const float* b_clf   = (const float*)d_in[11];
    const float* start_t = (const float*)d_in[12];
    const float* end_t   = (const float*)d_in[13];
    const float* trans   = (const float*)d_in[14];
    float* out = (float*)d_out;

    // reset per-launch state (graph-replay safe)
    void* psync = nullptr; void* phT = nullptr;
    cudaGetSymbolAddress(&psync, g_syncH);
    cudaGetSymbolAddress(&phT, g_hT2);
    cudaMemsetAsync(psync, 0, sizeof(unsigned) * 2 * 2 * Tz);
    cudaMemsetAsync(phT, 0, sizeof(float) * 2 * 2 * 2 * Hz * HB);

    prep_kernel<<<64, 256>>>(W_clf);
    xr_kernel<<<Tz * Bz, 192>>>(x);

    dim3 ggrid(Gz / 128, (Tz * Bz) / 128, 2);
    gemm_pre_kernel<<<ggrid, 256>>>(W_ih_f, W_ih_b, b_f, b_b);

    cudaFuncSetAttribute(lstm_persist, cudaFuncAttributeMaxDynamicSharedMemorySize,
                         SMEM_FLOATS * (int)sizeof(float));
    lstm_persist<<<NCTA, 256, SMEM_FLOATS * sizeof(float)>>>(W_hh_f, W_hh_b, lengths);

    emis_kernel<<<(Bz * Tz) / 8, 256>>>(b_clf);

    tail_kernel<<<64, 32>>>(lengths, targets, start_t, end_t, trans, out);
    finalize_kernel<<<1, 32>>>(out);
}